// round 5
// baseline (speedup 1.0000x reference)
#include <cuda_runtime.h>

#define NODES 7
#define CH 256
#define PAIRS 128               // CH/2 channel pairs
#define HID 128
#define P_TOTAL 65536           // 16*64*64
#define PF 4                    // prefetch depth (channel pairs)

__device__ float g_nw[2 * NODES * CH];   // new_weight [b, n, c]
__device__ float g_n2[2 * NODES];        // n2 [b, n]

typedef unsigned long long ull;

// ---------------------------------------------------------------------------
// Packed f32x2 helpers
// ---------------------------------------------------------------------------
__device__ __forceinline__ ull fma2(ull a, ull b, ull c) {
    ull d;
    asm("fma.rn.f32x2 %0, %1, %2, %3;" : "=l"(d) : "l"(a), "l"(b), "l"(c));
    return d;
}
__device__ __forceinline__ ull pack2(float x, float y) {
    ull r;
    asm("mov.b64 %0, {%1, %2};" : "=l"(r) : "f"(x), "f"(y));
    return r;
}
__device__ __forceinline__ void unpack2(ull v, float& x, float& y) {
    asm("mov.b64 {%0, %1}, %2;" : "=f"(x), "=f"(y) : "l"(v));
}
__device__ __forceinline__ float ldcs32(const float* p) {
    float v;
    asm volatile("ld.global.cs.b32 %0, [%1];" : "=f"(v) : "l"(p));
    return v;
}
__device__ __forceinline__ void stcs32(float* p, float v) {
    asm volatile("st.global.cs.b32 [%0], %1;" :: "l"(p), "f"(v));
}

// ---------------------------------------------------------------------------
// Precompute: new_weight = inp @ weight [2,7,256], n2 = inp @ nfh [2,7]
// ---------------------------------------------------------------------------
__global__ void precompute_kernel(const float* __restrict__ inp,
                                  const float* __restrict__ nfh,
                                  const float* __restrict__ weight) {
    int bn = blockIdx.x;            // 0..13
    int c  = threadIdx.x;           // 0..255
    __shared__ float sh_inp[HID];
    if (c < HID) sh_inp[c] = inp[bn * HID + c];
    __syncthreads();
    float acc = 0.f;
#pragma unroll 16
    for (int h = 0; h < HID; ++h)
        acc += sh_inp[h] * weight[h * CH + c];
    g_nw[bn * CH + c] = acc;
    if (c < 32) {
        float s = 0.f;
#pragma unroll
        for (int i = 0; i < 4; ++i)
            s += sh_inp[c + 32 * i] * nfh[c + 32 * i];
#pragma unroll
        for (int o = 16; o; o >>= 1)
            s += __shfl_xor_sync(0xffffffffu, s, o);
        if (c == 0) g_n2[bn] = s;
    }
}

// ---------------------------------------------------------------------------
// Fused main kernel: channel-split x2, TWO points per thread.
//   thread (half, pl) -> channels [128*half, 128*half+128)
//                        of points p0 = base+pl and p1 = base+128+pl
// Weight LDS.128 reads are shared between both points (halves L1 traffic).
// Grid: 512 blocks x 256 threads.
// ---------------------------------------------------------------------------
__global__ void __launch_bounds__(256, 3) main_kernel(
    const float* __restrict__ res,     // [2, 256, 65536]
    const float* __restrict__ Wres,    // [256, 7]
    float* __restrict__ out)           // [2, 256, 65536]
{
    __shared__ ull W2[PAIRS][8];          // (w[2k][n], w[2k+1][n])
    __shared__ ull NW2[PAIRS][8];         // (nw[n][2k], nw[n][2k+1])
    __shared__ ull part2[NODES][2][128];  // (p0 partial, p1 partial)

    const int tid  = threadIdx.x;
    const int half = tid >> 7;          // channel half 0/1
    const int pl   = tid & 127;
    const int b    = blockIdx.x >> 8;   // 0..1
    const int base = (blockIdx.x & 255) * 256;
    const int p    = base + pl;         // p and p+128 are this thread's points

    if (tid < PAIRS) {
        const int k = tid;
#pragma unroll
        for (int n = 0; n < NODES; ++n) {
            float w0 = Wres[(2 * k) * NODES + n];
            float w1 = Wres[(2 * k + 1) * NODES + n];
            W2[k][n] = pack2(w0, w1);
            float q0 = g_nw[(b * NODES + n) * CH + 2 * k];
            float q1 = g_nw[(b * NODES + n) * CH + 2 * k + 1];
            NW2[k][n] = pack2(q0, q1);
        }
        W2[k][7]  = 0ull;
        NW2[k][7] = 0ull;
    }
    float n2b = g_n2[b * NODES + 0];    // load all 7 below (kept scalar)
    float n2s[NODES];
#pragma unroll
    for (int n = 0; n < NODES; ++n) n2s[n] = g_n2[b * NODES + n];
    (void)n2b;
    __syncthreads();

    const int kbase = half * 64;
    const float* rfp = res + (size_t)b * CH * P_TOTAL
                           + (size_t)(half * 128) * P_TOTAL + p;

    ull acc0[NODES], acc1[NODES];
#pragma unroll
    for (int n = 0; n < NODES; ++n) { acc0[n] = 0ull; acc1[n] = 0ull; }

    // ---- Pass 1: 64 channel pairs, 2 points, shared weight reads
    float a0[2][PF], a1[2][PF];
#pragma unroll
    for (int i = 0; i < PF; ++i) {
#pragma unroll
        for (int pt = 0; pt < 2; ++pt) {
            a0[pt][i] = ldcs32(rfp + (size_t)(2 * i) * P_TOTAL + pt * 128);
            a1[pt][i] = ldcs32(rfp + (size_t)(2 * i + 1) * P_TOTAL + pt * 128);
        }
    }

#pragma unroll 1
    for (int jb = 0; jb < 64; jb += PF) {
#pragma unroll
        for (int i = 0; i < PF; ++i) {
            ull v0 = pack2(a0[0][i], a1[0][i]);
            ull v1 = pack2(a0[1][i], a1[1][i]);
            if (jb + PF < 64) {
                const int jn = jb + PF + i;
#pragma unroll
                for (int pt = 0; pt < 2; ++pt) {
                    a0[pt][i] = ldcs32(rfp + (size_t)(2 * jn) * P_TOTAL + pt * 128);
                    a1[pt][i] = ldcs32(rfp + (size_t)(2 * jn + 1) * P_TOTAL + pt * 128);
                }
            }
            const ulonglong2* wr = (const ulonglong2*)(&W2[kbase + jb + i][0]);
            ulonglong2 w01 = wr[0];
            ulonglong2 w23 = wr[1];
            ulonglong2 w45 = wr[2];
            ulonglong2 w6p = wr[3];
            acc0[0] = fma2(v0, w01.x, acc0[0]);  acc1[0] = fma2(v1, w01.x, acc1[0]);
            acc0[1] = fma2(v0, w01.y, acc0[1]);  acc1[1] = fma2(v1, w01.y, acc1[1]);
            acc0[2] = fma2(v0, w23.x, acc0[2]);  acc1[2] = fma2(v1, w23.x, acc1[2]);
            acc0[3] = fma2(v0, w23.y, acc0[3]);  acc1[3] = fma2(v1, w23.y, acc1[3]);
            acc0[4] = fma2(v0, w45.x, acc0[4]);  acc1[4] = fma2(v1, w45.x, acc1[4]);
            acc0[5] = fma2(v0, w45.y, acc0[5]);  acc1[5] = fma2(v1, w45.y, acc1[5]);
            acc0[6] = fma2(v0, w6p.x, acc0[6]);  acc1[6] = fma2(v1, w6p.x, acc1[6]);
        }
    }

    // ---- Exchange partial sums between channel halves (both points packed)
    float my0[NODES], my1[NODES];
#pragma unroll
    for (int n = 0; n < NODES; ++n) {
        float lo, hi;
        unpack2(acc0[n], lo, hi);  my0[n] = lo + hi;
        unpack2(acc1[n], lo, hi);  my1[n] = lo + hi;
        part2[n][half][pl] = pack2(my0[n], my1[n]);
    }
    __syncthreads();

    float s0[NODES], s1[NODES];
#pragma unroll
    for (int n = 0; n < NODES; ++n) {
        float o0, o1;
        unpack2(part2[n][half ^ 1][pl], o0, o1);
        s0[n] = my0[n] + o0 + n2s[n];
        s1[n] = my1[n] + o1 + n2s[n];
    }

    // ---- Softmax over 7 nodes, both points
    float m0 = s0[0], m1 = s1[0];
#pragma unroll
    for (int n = 1; n < NODES; ++n) { m0 = fmaxf(m0, s0[n]); m1 = fmaxf(m1, s1[n]); }
    float sum0 = 0.f, sum1 = 0.f;
    float e0[NODES], e1[NODES];
#pragma unroll
    for (int n = 0; n < NODES; ++n) {
        e0[n] = __expf(s0[n] - m0); sum0 += e0[n];
        e1[n] = __expf(s1[n] - m1); sum1 += e1[n];
    }
    float i0 = __fdividef(1.f, sum0);
    float i1 = __fdividef(1.f, sum1);
#pragma unroll
    for (int n = 0; n < NODES; ++n) {
        float a0f = e0[n] * i0;
        float a1f = e1[n] * i1;
        acc0[n] = pack2(a0f, a0f);      // reuse accumulators as attn
        acc1[n] = pack2(a1f, a1f);
    }

    // ---- Pass 2: 64 channel pairs x 2 points, shared NW2 reads
    float* op = out + (size_t)b * CH * P_TOTAL
                    + (size_t)(half * 128) * P_TOTAL + p;
#pragma unroll 2
    for (int j = 0; j < 64; ++j) {
        const ulonglong2* nr = (const ulonglong2*)(&NW2[kbase + j][0]);
        ulonglong2 q01 = nr[0];
        ulonglong2 q23 = nr[1];
        ulonglong2 q45 = nr[2];
        ulonglong2 q6p = nr[3];
        ull o0 = 0ull, o1 = 0ull;
        o0 = fma2(acc0[0], q01.x, o0);  o1 = fma2(acc1[0], q01.x, o1);
        o0 = fma2(acc0[1], q01.y, o0);  o1 = fma2(acc1[1], q01.y, o1);
        o0 = fma2(acc0[2], q23.x, o0);  o1 = fma2(acc1[2], q23.x, o1);
        o0 = fma2(acc0[3], q23.y, o0);  o1 = fma2(acc1[3], q23.y, o1);
        o0 = fma2(acc0[4], q45.x, o0);  o1 = fma2(acc1[4], q45.x, o1);
        o0 = fma2(acc0[5], q45.y, o0);  o1 = fma2(acc1[5], q45.y, o1);
        o0 = fma2(acc0[6], q6p.x, o0);  o1 = fma2(acc1[6], q6p.x, o1);
        float v0, v1;
        unpack2(o0, v0, v1);
        stcs32(op + (size_t)(2 * j) * P_TOTAL,     fmaxf(v0, 0.f));
        stcs32(op + (size_t)(2 * j + 1) * P_TOTAL, fmaxf(v1, 0.f));
        unpack2(o1, v0, v1);
        stcs32(op + (size_t)(2 * j) * P_TOTAL + 128,     fmaxf(v0, 0.f));
        stcs32(op + (size_t)(2 * j + 1) * P_TOTAL + 128, fmaxf(v1, 0.f));
    }
}

// ---------------------------------------------------------------------------
extern "C" void kernel_launch(void* const* d_in, const int* in_sizes, int n_in,
                              void* d_out, int out_size) {
    const float* inp    = (const float*)d_in[0];  // [1,2,7,128]
    const float* res    = (const float*)d_in[1];  // [2,256,16,64,64]
    const float* Wres   = (const float*)d_in[2];  // [256,7]
    const float* nfh    = (const float*)d_in[3];  // [128,1]
    const float* weight = (const float*)d_in[4];  // [128,256]

    precompute_kernel<<<14, 256>>>(inp, nfh, weight);
    main_kernel<<<512, 256>>>(res, Wres, (float*)d_out);
}